// round 3
// baseline (speedup 1.0000x reference)
#include <cuda_runtime.h>
#include <math.h>

#define BB  256
#define TT  168
#define INF 64
#define HH  512
#define HOR 24

// ---- device scratch (no allocations allowed) ----
__device__ float g_h[2][2][BB * HH];   // [layer][pingpong][B*H]
__device__ float g_c[2][BB * HH];      // [layer][B*H]  (updated in place)
__device__ float g_xin[BB];            // decoder scalar feedback

__device__ __forceinline__ float sigmoidf_(float x) { return 1.0f / (1.0f + expf(-x)); }

__global__ void init_state_kernel() {
    int i = blockIdx.x * blockDim.x + threadIdx.x;
    if (i < BB * HH) {
        g_h[0][0][i] = 0.0f;
        g_h[1][0][i] = 0.0f;
        g_c[0][i]    = 0.0f;
        g_c[1][i]    = 0.0f;
    }
    if (i < BB) g_xin[i] = 0.0f;
}

// Fused LSTM step:
//   gates = [Xin | h_prev] @ [Wih | Whh]^T + bias (+ xin_scalar * Wscal)
//   c = sig(f)*c + sig(i)*tanh(g);  h_out = sig(o)*tanh(c)
// Tile: BM=32 batch rows x BN=32 hidden cols x 4 gates. 256 threads, 2x2x4 micro-tile.
// grid = (16, 8): blockIdx.x = hidden tile (512/32), blockIdx.y = batch tile (256/32)
__global__ __launch_bounds__(256) void lstm_step_kernel(
    const float* __restrict__ Xin, int Kx, int xstride,
    const float* __restrict__ Wih,                              // [2048, Kx]
    const float* __restrict__ xin_scalar,                       // [B] or null
    const float* __restrict__ Wscal,                            // [2048] (Wih with K=1)
    const float* __restrict__ Whh,                              // [2048, 512]
    const float* __restrict__ bias,                             // [2048]
    const float* __restrict__ h_prev,                           // [B, 512]
    float* __restrict__ h_out,                                  // [B, 512]
    float* __restrict__ c_state)                                // [B, 512] in/out
{
    __shared__ __align__(16) float As[32][34];        // [k][m], padded
    __shared__ __align__(16) float Ws[4][32][34];     // [gate][k][n], padded

    const int tid = threadIdx.x;
    const int tx = tid & 15;          // 0..15  (hidden cols / 2)
    const int ty = tid >> 4;          // 0..15  (batch rows / 2)
    const int bn = blockIdx.x;        // hidden tile
    const int bm = blockIdx.y;        // batch tile
    const int row0 = bm * 32 + ty * 2;
    const int col0 = bn * 32 + tx * 2;

    float acc[4][2][2];
#pragma unroll
    for (int g = 0; g < 4; g++) {
        float b0 = bias[g * HH + col0];
        float b1 = bias[g * HH + col0 + 1];
        acc[g][0][0] = b0; acc[g][0][1] = b1;
        acc[g][1][0] = b0; acc[g][1][1] = b1;
    }

    const int lk = tid & 31;          // k within K-tile
    const int lm = tid >> 5;          // 0..7

#pragma unroll 1
    for (int seg = 0; seg < 2; seg++) {
        const float* Aptr = (seg == 0) ? Xin : h_prev;
        const float* Wptr = (seg == 0) ? Wih : Whh;
        const int Kseg    = (seg == 0) ? Kx  : HH;
        const int astr    = (seg == 0) ? xstride : HH;
        if (Kseg == 0) continue;
#pragma unroll 1
        for (int kt = 0; kt < Kseg; kt += 32) {
            // load A tile (32 rows x 32 k), store transposed As[k][m]
#pragma unroll
            for (int r = 0; r < 4; r++) {
                int m = lm + r * 8;
                As[lk][m] = Aptr[(bm * 32 + m) * astr + kt + lk];
            }
            // load W tiles for 4 gates: Ws[g][k][n]
#pragma unroll
            for (int g = 0; g < 4; g++) {
#pragma unroll
                for (int r = 0; r < 4; r++) {
                    int n = lm + r * 8;
                    Ws[g][lk][n] = Wptr[(g * HH + bn * 32 + n) * Kseg + kt + lk];
                }
            }
            __syncthreads();
#pragma unroll
            for (int k = 0; k < 32; k++) {
                float2 a = *(const float2*)&As[k][ty * 2];
#pragma unroll
                for (int g = 0; g < 4; g++) {
                    float2 w = *(const float2*)&Ws[g][k][tx * 2];
                    acc[g][0][0] += a.x * w.x;
                    acc[g][0][1] += a.x * w.y;
                    acc[g][1][0] += a.y * w.x;
                    acc[g][1][1] += a.y * w.y;
                }
            }
            __syncthreads();
        }
    }

    // decoder layer-0 scalar input (K=1)
    if (xin_scalar) {
        float x0 = xin_scalar[row0];
        float x1 = xin_scalar[row0 + 1];
#pragma unroll
        for (int g = 0; g < 4; g++) {
            float w0 = Wscal[g * HH + col0];
            float w1 = Wscal[g * HH + col0 + 1];
            acc[g][0][0] += x0 * w0; acc[g][0][1] += x0 * w1;
            acc[g][1][0] += x1 * w0; acc[g][1][1] += x1 * w1;
        }
    }

    // fused activations + state update (PyTorch gate order i,f,g,o)
#pragma unroll
    for (int i = 0; i < 2; i++) {
#pragma unroll
        for (int j = 0; j < 2; j++) {
            int idx = (row0 + i) * HH + col0 + j;
            float ig = sigmoidf_(acc[0][i][j]);
            float fg = sigmoidf_(acc[1][i][j]);
            float gg = tanhf(acc[2][i][j]);
            float og = sigmoidf_(acc[3][i][j]);
            float c  = fg * c_state[idx] + ig * gg;
            c_state[idx] = c;
            h_out[idx]   = og * tanhf(c);
        }
    }
}

// out[b, s] = h1[b,:] . fcW + fcb ; also feeds back into g_xin
__global__ void fc_kernel(const float* __restrict__ h1,
                          const float* __restrict__ fcW,
                          const float* __restrict__ fcb,
                          float* __restrict__ out, int s)
{
    int warp = threadIdx.x >> 5;
    int lane = threadIdx.x & 31;
    int b = blockIdx.x * 4 + warp;
    const float* hrow = h1 + b * HH;
    float sum = 0.0f;
#pragma unroll
    for (int k = lane; k < HH; k += 32) sum += hrow[k] * fcW[k];
#pragma unroll
    for (int o = 16; o; o >>= 1) sum += __shfl_xor_sync(0xffffffffu, sum, o);
    if (lane == 0) {
        float v = sum + fcb[0];
        out[b * HOR + s] = v;
        g_xin[b] = v;
    }
}

extern "C" void kernel_launch(void* const* d_in, const int* in_sizes, int n_in,
                              void* d_out, int out_size)
{
    const float* x        = (const float*)d_in[0];
    // d_in[1] = y : unused by the reference
    const float* eWih0 = (const float*)d_in[2];
    const float* eWhh0 = (const float*)d_in[3];
    const float* eb0   = (const float*)d_in[4];
    const float* eWih1 = (const float*)d_in[5];
    const float* eWhh1 = (const float*)d_in[6];
    const float* eb1   = (const float*)d_in[7];
    const float* dWih0 = (const float*)d_in[8];   // [2048,1]
    const float* dWhh0 = (const float*)d_in[9];
    const float* db0   = (const float*)d_in[10];
    const float* dWih1 = (const float*)d_in[11];
    const float* dWhh1 = (const float*)d_in[12];
    const float* db1   = (const float*)d_in[13];
    const float* fcW   = (const float*)d_in[14];
    const float* fcb   = (const float*)d_in[15];
    float* out = (float*)d_out;

    void* p;
    cudaGetSymbolAddress(&p, g_h);
    float* hbase = (float*)p;
    float* h0[2] = { hbase,              hbase + BB * HH };
    float* h1[2] = { hbase + 2 * BB * HH, hbase + 3 * BB * HH };
    cudaGetSymbolAddress(&p, g_c);
    float* c0 = (float*)p;
    float* c1 = c0 + BB * HH;
    cudaGetSymbolAddress(&p, g_xin);
    float* xin = (float*)p;

    init_state_kernel<<<(BB * HH + 255) / 256, 256>>>();

    dim3 grid(16, 8);   // (hidden tiles, batch tiles)
    int cur = 0;

    // ---- encoder: 168 steps x 2 layers ----
    for (int t = 0; t < TT; t++) {
        lstm_step_kernel<<<grid, 256>>>(
            x + t * INF, INF, TT * INF, eWih0,
            nullptr, nullptr,
            eWhh0, eb0, h0[cur], h0[cur ^ 1], c0);
        lstm_step_kernel<<<grid, 256>>>(
            h0[cur ^ 1], HH, HH, eWih1,
            nullptr, nullptr,
            eWhh1, eb1, h1[cur], h1[cur ^ 1], c1);
        cur ^= 1;
    }

    // ---- decoder: 24 autoregressive steps ----
    for (int s = 0; s < HOR; s++) {
        lstm_step_kernel<<<grid, 256>>>(
            nullptr, 0, 0, nullptr,
            xin, dWih0,
            dWhh0, db0, h0[cur], h0[cur ^ 1], c0);
        lstm_step_kernel<<<grid, 256>>>(
            h0[cur ^ 1], HH, HH, dWih1,
            nullptr, nullptr,
            dWhh1, db1, h1[cur], h1[cur ^ 1], c1);
        fc_kernel<<<64, 128>>>(h1[cur ^ 1], fcW, fcb, out, s);
        cur ^= 1;
    }
}

// round 4
// speedup vs baseline: 1.2282x; 1.2282x over previous
#include <cuda_runtime.h>
#include <math.h>
#include <stdint.h>

#define BB  256
#define TT  168
#define INF 64
#define HH  512
#define HOR 24

// ---- device scratch (no allocations allowed) ----
__device__ float g_h[2][2][BB * HH];   // [layer][pingpong][B*H]
__device__ float g_c[2][BB * HH];      // [layer][B*H]  (updated in place)
__device__ float g_xin[BB];            // decoder scalar feedback

__device__ __forceinline__ float sigmoidf_(float x) { return 1.0f / (1.0f + expf(-x)); }

__global__ void init_state_kernel() {
    int i = blockIdx.x * blockDim.x + threadIdx.x;
    if (i < BB * HH) {
        g_h[0][0][i] = 0.0f;
        g_h[1][0][i] = 0.0f;
        g_c[0][i]    = 0.0f;
        g_c[1][i]    = 0.0f;
    }
    if (i < BB) g_xin[i] = 0.0f;
}

// ---------------------------------------------------------------------------
// Fused LSTM step, cp.async double-buffered.
//   gates = [Xin | h_prev] @ [Wih | Whh]^T + bias (+ xin_scalar * Wscal)
//   c = sig(f)*c + sig(i)*tanh(g);  h_out = sig(o)*tanh(c)
// Block: 512 threads. Tile: BM=32 batch rows x 32 hidden cols x 4 gates.
// Thread micro-tile: 2 rows x 1 col x 4 gates = 8 accumulators.
// grid = (16, 8): blockIdx.x = hidden tile, blockIdx.y = batch tile.
// smem per k-tile buffer: As[32 rows][36 words] + Ws[128 gate-rows][36 words]
// (row stride 36 words = 144B: 16B-aligned, LDS.128 phase-conflict-free)
// ---------------------------------------------------------------------------

#define ROWPAD 36
#define A_WORDS (32 * ROWPAD)      // 1152
#define W_WORDS (128 * ROWPAD)     // 4608
#define BUF_WORDS (A_WORDS + W_WORDS)  // 5760

__device__ __forceinline__ void cpasync16(uint32_t s, const void* g) {
    asm volatile("cp.async.cg.shared.global [%0], [%1], 16;\n" :: "r"(s), "l"(g));
}
__device__ __forceinline__ void cpasync_commit() {
    asm volatile("cp.async.commit_group;\n");
}
__device__ __forceinline__ void cpasync_wait0() {
    asm volatile("cp.async.wait_group 0;\n");
}

// Load one 32-k tile: W chunk ids 0..1023 (128 gate-rows x 8 float4),
// A chunk ids 1024..1279 (32 rows x 8 float4). 512 threads.
__device__ __forceinline__ void load_tile(
    uint32_t sbase,                 // smem u32 address of this buffer
    const float* __restrict__ Ap, int astr, int aoff,
    const float* __restrict__ Wp, int wstr, int woff,
    int bm, int bn, int tid)
{
#pragma unroll
    for (int it = 0; it < 3; it++) {
        if (it == 2 && tid >= 256) break;
        int c = tid + it * 512;
        if (c < 1024) {
            int r  = c >> 3;        // 0..127 : g*32 + n
            int k4 = c & 7;
            int g  = r >> 5;
            int n  = r & 31;
            const float* gp = Wp + (size_t)(g * HH + bn * 32 + n) * wstr + woff + k4 * 4;
            cpasync16(sbase + (uint32_t)(A_WORDS + r * ROWPAD + k4 * 4) * 4u, gp);
        } else {
            int c2 = c - 1024;
            int m  = c2 >> 3;       // 0..31
            int k4 = c2 & 7;
            const float* gp = Ap + (size_t)(bm * 32 + m) * astr + aoff + k4 * 4;
            cpasync16(sbase + (uint32_t)(m * ROWPAD + k4 * 4) * 4u, gp);
        }
    }
}

__global__ __launch_bounds__(512) void lstm_step_kernel(
    const float* __restrict__ Xin, int Kx, int xstride,
    const float* __restrict__ Wih,                              // [2048, Kx]
    const float* __restrict__ xin_scalar,                       // [B] or null
    const float* __restrict__ Wscal,                            // [2048] (Wih with K=1)
    const float* __restrict__ Whh,                              // [2048, 512]
    const float* __restrict__ bias,                             // [2048]
    const float* __restrict__ h_prev,                           // [B, 512]
    float* __restrict__ h_out,                                  // [B, 512]
    float* __restrict__ c_state)                                // [B, 512] in/out
{
    __shared__ __align__(16) float smem[2][BUF_WORDS];

    const int tid = threadIdx.x;
    const int nx  = tid & 31;         // hidden col within tile
    const int ty  = tid >> 5;         // 0..15 -> row pair (== warp id)
    const int bn  = blockIdx.x;
    const int bm  = blockIdx.y;
    const int row0 = bm * 32 + ty * 2;
    const int col  = bn * 32 + nx;

    // prefetch c state (hides epilogue latency)
    const int idx0 = row0 * HH + col;
    const int idx1 = idx0 + HH;
    float cpre0 = c_state[idx0];
    float cpre1 = c_state[idx1];

    float acc[4][2];
#pragma unroll
    for (int g = 0; g < 4; g++) {
        float b = bias[g * HH + col];
        acc[g][0] = b;
        acc[g][1] = b;
    }

    uint32_t smem_u32;
    {
        void* p = (void*)&smem[0][0];
        asm("{ .reg .u64 t; cvta.to.shared.u64 t, %1; cvt.u32.u64 %0, t; }"
            : "=r"(smem_u32) : "l"(p));
    }

    const int ntiles = (Kx + HH) >> 5;   // 32-k tiles total across both segments

    // resolve a tile index into (source, offset)
    auto resolve = [&](int tile, const float*& Ap, int& astr, int& aoff,
                       const float*& Wp, int& wstr, int& woff) {
        int kt = tile * 32;
        if (kt < Kx) {
            Ap = Xin; astr = xstride; aoff = kt;
            Wp = Wih; wstr = Kx;      woff = kt;
        } else {
            Ap = h_prev; astr = HH; aoff = kt - Kx;
            Wp = Whh;    wstr = HH; woff = kt - Kx;
        }
    };

    // prologue: load tile 0 into buffer 0
    {
        const float *Ap, *Wp; int astr, aoff, wstr, woff;
        resolve(0, Ap, astr, aoff, Wp, wstr, woff);
        load_tile(smem_u32, Ap, astr, aoff, Wp, wstr, woff, bm, bn, tid);
        cpasync_commit();
    }

#pragma unroll 1
    for (int t = 0; t < ntiles; t++) {
        cpasync_wait0();          // this thread's tile t is in smem
        __syncthreads();          // everyone's tile t visible; prior compute done

        if (t + 1 < ntiles) {     // stream next tile into the other buffer
            const float *Ap, *Wp; int astr, aoff, wstr, woff;
            resolve(t + 1, Ap, astr, aoff, Wp, wstr, woff);
            load_tile(smem_u32 + (uint32_t)((t + 1) & 1) * BUF_WORDS * 4u,
                      Ap, astr, aoff, Wp, wstr, woff, bm, bn, tid);
        }
        cpasync_commit();

        const float* sb = &smem[t & 1][0];
        const float* Asb = sb + ty * 2 * ROWPAD;
        const float* Wsb = sb + A_WORDS + nx * ROWPAD;

#pragma unroll
        for (int kg = 0; kg < 8; kg++) {
            float4 a0 = *(const float4*)(Asb + kg * 4);
            float4 a1 = *(const float4*)(Asb + ROWPAD + kg * 4);
#pragma unroll
            for (int g = 0; g < 4; g++) {
                float4 w = *(const float4*)(Wsb + g * 32 * ROWPAD + kg * 4);
                acc[g][0] += a0.x * w.x;
                acc[g][0] += a0.y * w.y;
                acc[g][0] += a0.z * w.z;
                acc[g][0] += a0.w * w.w;
                acc[g][1] += a1.x * w.x;
                acc[g][1] += a1.y * w.y;
                acc[g][1] += a1.z * w.z;
                acc[g][1] += a1.w * w.w;
            }
        }
    }

    // decoder layer-0 scalar input (K=1)
    if (xin_scalar) {
        float x0 = xin_scalar[row0];
        float x1 = xin_scalar[row0 + 1];
#pragma unroll
        for (int g = 0; g < 4; g++) {
            float w = Wscal[g * HH + col];
            acc[g][0] += x0 * w;
            acc[g][1] += x1 * w;
        }
    }

    // fused activations + state update (PyTorch gate order i,f,g,o)
    {
        float ig = sigmoidf_(acc[0][0]);
        float fg = sigmoidf_(acc[1][0]);
        float gg = tanhf(acc[2][0]);
        float og = sigmoidf_(acc[3][0]);
        float c  = fg * cpre0 + ig * gg;
        c_state[idx0] = c;
        h_out[idx0]   = og * tanhf(c);
    }
    {
        float ig = sigmoidf_(acc[0][1]);
        float fg = sigmoidf_(acc[1][1]);
        float gg = tanhf(acc[2][1]);
        float og = sigmoidf_(acc[3][1]);
        float c  = fg * cpre1 + ig * gg;
        c_state[idx1] = c;
        h_out[idx1]   = og * tanhf(c);
    }
}

// out[b, s] = h1[b,:] . fcW + fcb ; also feeds back into g_xin
__global__ void fc_kernel(const float* __restrict__ h1,
                          const float* __restrict__ fcW,
                          const float* __restrict__ fcb,
                          float* __restrict__ out, int s)
{
    int warp = threadIdx.x >> 5;
    int lane = threadIdx.x & 31;
    int b = blockIdx.x * 4 + warp;
    const float* hrow = h1 + b * HH;
    float sum = 0.0f;
#pragma unroll
    for (int k = lane; k < HH; k += 32) sum += hrow[k] * fcW[k];
#pragma unroll
    for (int o = 16; o; o >>= 1) sum += __shfl_xor_sync(0xffffffffu, sum, o);
    if (lane == 0) {
        float v = sum + fcb[0];
        out[b * HOR + s] = v;
        g_xin[b] = v;
    }
}

extern "C" void kernel_launch(void* const* d_in, const int* in_sizes, int n_in,
                              void* d_out, int out_size)
{
    const float* x     = (const float*)d_in[0];
    // d_in[1] = y : unused by the reference
    const float* eWih0 = (const float*)d_in[2];
    const float* eWhh0 = (const float*)d_in[3];
    const float* eb0   = (const float*)d_in[4];
    const float* eWih1 = (const float*)d_in[5];
    const float* eWhh1 = (const float*)d_in[6];
    const float* eb1   = (const float*)d_in[7];
    const float* dWih0 = (const float*)d_in[8];   // [2048,1]
    const float* dWhh0 = (const float*)d_in[9];
    const float* db0   = (const float*)d_in[10];
    const float* dWih1 = (const float*)d_in[11];
    const float* dWhh1 = (const float*)d_in[12];
    const float* db1   = (const float*)d_in[13];
    const float* fcW   = (const float*)d_in[14];
    const float* fcb   = (const float*)d_in[15];
    float* out = (float*)d_out;

    void* p;
    cudaGetSymbolAddress(&p, g_h);
    float* hbase = (float*)p;
    float* h0[2] = { hbase,               hbase + BB * HH };
    float* h1[2] = { hbase + 2 * BB * HH, hbase + 3 * BB * HH };
    cudaGetSymbolAddress(&p, g_c);
    float* c0 = (float*)p;
    float* c1 = c0 + BB * HH;
    cudaGetSymbolAddress(&p, g_xin);
    float* xin = (float*)p;

    init_state_kernel<<<(BB * HH + 255) / 256, 256>>>();

    dim3 grid(16, 8);   // (hidden tiles, batch tiles)
    int cur = 0;

    // ---- encoder: 168 steps x 2 layers ----
    for (int t = 0; t < TT; t++) {
        lstm_step_kernel<<<grid, 512>>>(
            x + t * INF, INF, TT * INF, eWih0,
            nullptr, nullptr,
            eWhh0, eb0, h0[cur], h0[cur ^ 1], c0);
        lstm_step_kernel<<<grid, 512>>>(
            h0[cur ^ 1], HH, HH, eWih1,
            nullptr, nullptr,
            eWhh1, eb1, h1[cur], h1[cur ^ 1], c1);
        cur ^= 1;
    }

    // ---- decoder: 24 autoregressive steps ----
    for (int s = 0; s < HOR; s++) {
        lstm_step_kernel<<<grid, 512>>>(
            nullptr, 0, 0, nullptr,
            xin, dWih0,
            dWhh0, db0, h0[cur], h0[cur ^ 1], c0);
        lstm_step_kernel<<<grid, 512>>>(
            h0[cur ^ 1], HH, HH, dWih1,
            nullptr, nullptr,
            dWhh1, db1, h1[cur], h1[cur ^ 1], c1);
        fc_kernel<<<64, 128>>>(h1[cur ^ 1], fcW, fcb, out, s);
        cur ^= 1;
    }
}